// round 13
// baseline (speedup 1.0000x reference)
#include <cuda_runtime.h>
#include <cuda_fp16.h>
#include <cstdint>

// ---------------------------------------------------------------------------
// GCN (3-layer) on GB300 — CSR gather, fp16 intermediates, chunk-pipelined.
//   L1: xw = H @ W (UNscaled fp16); gather1 applies dinv[neighbor] per edge.
//   L2/3: xw = (H @ W) * dinv[row] (fp16); gathers add prescaled rows.
//   Buffers rotate A -> B -> C -> B -> A so gather(N) and GEMM(N+1) can
//   overlap on disjoint chunks without write-after-read hazards.
// ---------------------------------------------------------------------------

#define N_MAX 100000
#define E_MAX 1600000

static __device__ __align__(256) __half2 g_bufA[(size_t)N_MAX * 32];  // stride 32
static __device__ __align__(256) __half2 g_bufB[(size_t)N_MAX * 32];
static __device__ __align__(256) __half2 g_bufC[(size_t)N_MAX * 32];
static __device__ __align__(256) float g_dinv[N_MAX];
static __device__ int g_degi[N_MAX];
static __device__ int g_cursor[N_MAX];
static __device__ int g_ptr[N_MAX + 1];
static __device__ int g_bsum[1024];
static __device__ int g_erow[E_MAX];
static __device__ int g_mode;  // 0 = int64 indices, 1 = int32 indices

// ---------------- dtype detection ----------------
__global__ void detect_mode_kernel(const void* ei, int cnt64, int n) {
    __shared__ int bad;
    if (threadIdx.x == 0) bad = 0;
    __syncthreads();
    const long long* p = (const long long*)ei;
    int cnt = min(cnt64, 1024);
    for (int i = threadIdx.x; i < cnt; i += blockDim.x) {
        unsigned long long v = (unsigned long long)p[i];
        if (v >= (unsigned long long)n) atomicOr(&bad, 1);
    }
    __syncthreads();
    if (threadIdx.x == 0) g_mode = bad ? 1 : 0;
}

__device__ __forceinline__ int edge_idx(const void* ei, long long pos, int mode) {
    return mode ? ((const int*)ei)[pos] : (int)((const long long*)ei)[pos];
}

// ---------------- CSR build ----------------

__global__ void deg_count_kernel(int* degi, const void* ei, int E, int n) {
    int e = blockIdx.x * blockDim.x + threadIdx.x;
    if (e < E) {
        int mode = g_mode;
        unsigned c = (unsigned)edge_idx(ei, (long long)E + e, mode);  // col
        if (c < (unsigned)n) atomicAdd(&degi[c], 1);
    }
}

__global__ void scanA_kernel(const int* degi, int* ptr, int* bsum, int n) {
    __shared__ int s[256];
    int i = blockIdx.x * 256 + threadIdx.x;
    int v = (i < n) ? degi[i] : 0;
    s[threadIdx.x] = v;
    __syncthreads();
    for (int off = 1; off < 256; off <<= 1) {
        int t = (threadIdx.x >= off) ? s[threadIdx.x - off] : 0;
        __syncthreads();
        s[threadIdx.x] += t;
        __syncthreads();
    }
    if (i < n) ptr[i] = s[threadIdx.x] - v;   // exclusive within block
    if (threadIdx.x == 255) bsum[blockIdx.x] = s[255];
}

__global__ void scanB_kernel(int* bsum, int nb) {
    __shared__ int s[1024];
    int v = (threadIdx.x < nb) ? bsum[threadIdx.x] : 0;
    s[threadIdx.x] = v;
    __syncthreads();
    for (int off = 1; off < 1024; off <<= 1) {
        int t = (threadIdx.x >= off) ? s[threadIdx.x - off] : 0;
        __syncthreads();
        s[threadIdx.x] += t;
        __syncthreads();
    }
    if (threadIdx.x < nb) bsum[threadIdx.x] = s[threadIdx.x] - v;  // exclusive
}

__global__ void scanC_fused_kernel(int* ptr, const int* bsum, int* cursor,
                                   float* dinv, const int* degi, int n, int E) {
    int i = blockIdx.x * 256 + threadIdx.x;
    if (i < n) {
        int p = ptr[i] + bsum[blockIdx.x];
        ptr[i] = p;
        cursor[i] = p;
        dinv[i] = rsqrtf(1.0f + (float)degi[i]);     // +1 self loop
    }
    if (i == 0) ptr[n] = E;
}

__global__ void fill_kernel(const void* ei, int* cursor, int* erow, int E, int n) {
    int e = blockIdx.x * blockDim.x + threadIdx.x;
    if (e < E) {
        int mode = g_mode;
        unsigned r = (unsigned)edge_idx(ei, e, mode);
        unsigned c = (unsigned)edge_idx(ei, (long long)E + e, mode);
        if (r >= (unsigned)n || c >= (unsigned)n) return;
        int pos = atomicAdd(&cursor[c], 1);
        erow[pos] = (int)r;
    }
}

// ---------------- GEMM (+ optional dinv[row] scale) -> half2, stride 32 -----
// Processes node range [row0, row1).

__device__ __forceinline__ void fma2(unsigned long long& d,
                                     unsigned long long a,
                                     unsigned long long b) {
    asm("fma.rn.f32x2 %0, %1, %2, %3;" : "=l"(d) : "l"(a), "l"(b), "l"(d));
}

template <int DIN, int DOUT, bool HALF_IN, bool SCALE>
__global__ void gemm_kernel(const void* __restrict__ Xv,
                            const float* __restrict__ W,
                            const float* __restrict__ dinv,
                            __half2* __restrict__ xwh,
                            int row0, int row1) {
    __shared__ __align__(16) float Ws[DIN * DOUT];
    const int tid = threadIdx.x;           // 0..127
    const int row = row0 + blockIdx.x * 128 + tid;

    for (int i = tid; i < DIN * DOUT; i += 128) Ws[i] = W[i];
    __syncthreads();

    unsigned long long a2[DOUT / 2];
#pragma unroll
    for (int j = 0; j < DOUT / 2; j++) a2[j] = 0ull;

    const bool act = (row < row1);

#pragma unroll
    for (int k0 = 0; k0 < DIN; k0 += 16) {
        float xr[16];
        if (act) {
            if (HALF_IN) {
                const uint4* src = (const uint4*)((const __half*)Xv + (size_t)row * DIN + k0);
                uint4 u0 = __ldg(src);
                uint4 u1 = __ldg(src + 1);
                const unsigned* uu = &u0.x;
#pragma unroll
                for (int q = 0; q < 4; q++) {
                    float2 f = __half22float2(*(const __half2*)&uu[q]);
                    xr[q * 2] = f.x; xr[q * 2 + 1] = f.y;
                }
                const unsigned* vv = &u1.x;
#pragma unroll
                for (int q = 0; q < 4; q++) {
                    float2 f = __half22float2(*(const __half2*)&vv[q]);
                    xr[8 + q * 2] = f.x; xr[8 + q * 2 + 1] = f.y;
                }
            } else {
                const float4* src = (const float4*)((const float*)Xv + (size_t)row * DIN + k0);
#pragma unroll
                for (int q = 0; q < 4; q++) {
                    float4 v = __ldg(src + q);
                    xr[q * 4] = v.x; xr[q * 4 + 1] = v.y;
                    xr[q * 4 + 2] = v.z; xr[q * 4 + 3] = v.w;
                }
            }
        } else {
#pragma unroll
            for (int q = 0; q < 16; q++) xr[q] = 0.f;
        }
#pragma unroll
        for (int k = 0; k < 16; k++) {
            unsigned long long xv2;
            asm("mov.b64 %0, {%1, %2};" : "=l"(xv2) : "f"(xr[k]), "f"(xr[k]));
            const float* wrow = &Ws[(k0 + k) * DOUT];
#pragma unroll
            for (int j = 0; j < DOUT; j += 4) {
                ulonglong2 ww = *(const ulonglong2*)&wrow[j];
                fma2(a2[j / 2],     xv2, ww.x);
                fma2(a2[j / 2 + 1], xv2, ww.y);
            }
        }
    }

    if (act) {
        float s = SCALE ? dinv[row] : 1.0f;
        __half2* dst = xwh + (size_t)row * 32;      // padded stride
#pragma unroll
        for (int p = 0; p < DOUT / 2; p += 2) {
            float x0, x1, x2, x3;
            asm("mov.b64 {%0, %1}, %2;" : "=f"(x0), "=f"(x1) : "l"(a2[p]));
            asm("mov.b64 {%0, %1}, %2;" : "=f"(x2), "=f"(x3) : "l"(a2[p + 1]));
            uint2 pack;
            __half2 h0 = __floats2half2_rn(x0 * s, x1 * s);
            __half2 h1 = __floats2half2_rn(x2 * s, x3 * s);
            pack.x = *(unsigned*)&h0;
            pack.y = *(unsigned*)&h1;
            *(uint2*)&dst[p] = pack;
        }
    }
}

// ---------------- gather-reduce + fused epilogue (warp per node) ------------
// Processes node range [node0, node1). NSCALE: apply dinv[neighbor] per edge.

template <bool NSCALE>
__global__ void gather64h_kernel(const __half2* __restrict__ xwh,
                                 const int* __restrict__ ptr,
                                 const int* __restrict__ erow,
                                 const float* __restrict__ dinv,
                                 const float* __restrict__ b,
                                 __half2* __restrict__ out,
                                 int node0, int node1) {
    int lane = threadIdx.x & 31;
    int node = node0 + blockIdx.x * 8 + (threadIdx.x >> 5);
    if (node >= node1) return;

    int start = __ldg(&ptr[node]);
    int end   = __ldg(&ptr[node + 1]);
    float sn = __ldg(&dinv[node]);

    float2 self = __half22float2(__ldg(&xwh[(size_t)node * 32 + lane]));
    float2 acc;
    if (NSCALE) { acc.x = self.x * sn; acc.y = self.y * sn; }
    else        { acc = self; }

    int cnt = end - start;
    int j = start, j8 = start + (cnt & ~7);
    for (; j < j8; j += 8) {
        int ids[8];
#pragma unroll
        for (int k = 0; k < 8; k++) ids[k] = __ldg(&erow[j + k]);
#pragma unroll
        for (int k = 0; k < 8; k++) {
            float2 f = __half22float2(__ldg(&xwh[(size_t)ids[k] * 32 + lane]));
            if (NSCALE) {
                float sr = __ldg(&dinv[ids[k]]);
                acc.x += f.x * sr; acc.y += f.y * sr;
            } else {
                acc.x += f.x; acc.y += f.y;
            }
        }
    }
    for (; j < end; j++) {
        int id = __ldg(&erow[j]);
        float2 f = __half22float2(__ldg(&xwh[(size_t)id * 32 + lane]));
        if (NSCALE) {
            float sr = __ldg(&dinv[id]);
            acc.x += f.x * sr; acc.y += f.y * sr;
        } else {
            acc.x += f.x; acc.y += f.y;
        }
    }

    float2 bb = __ldg((const float2*)b + lane);
    float ox = fmaxf(acc.x * sn + bb.x, 0.f);
    float oy = fmaxf(acc.y * sn + bb.y, 0.f);
    out[(size_t)node * 32 + lane] = __floats2half2_rn(ox, oy);
}

// D=40 final layer: 20 threads/node, xw stride 32 half2 (prescaled), fp32 out.

__global__ void gather40_kernel(const __half2* __restrict__ xwh,
                                const int* __restrict__ ptr,
                                const int* __restrict__ erow,
                                const float* __restrict__ dinv,
                                const float* __restrict__ b,
                                float* __restrict__ out,
                                int n) {
    int tid = threadIdx.x;
    if (tid >= 240) return;                  // 12 nodes * 20 threads
    int nl = tid / 20;
    int lane = tid - nl * 20;                // feature pair 0..19
    int node = blockIdx.x * 12 + nl;
    if (node >= n) return;

    int start = __ldg(&ptr[node]);
    int end   = __ldg(&ptr[node + 1]);

    float2 acc = __half22float2(__ldg(&xwh[(size_t)node * 32 + lane]));  // self

    int cnt = end - start;
    int j = start, j8 = start + (cnt & ~7);
    for (; j < j8; j += 8) {
        int ids[8];
#pragma unroll
        for (int k = 0; k < 8; k++) ids[k] = __ldg(&erow[j + k]);
#pragma unroll
        for (int k = 0; k < 8; k++) {
            float2 f = __half22float2(__ldg(&xwh[(size_t)ids[k] * 32 + lane]));
            acc.x += f.x; acc.y += f.y;
        }
    }
    for (; j < end; j++) {
        float2 f = __half22float2(__ldg(&xwh[(size_t)__ldg(&erow[j]) * 32 + lane]));
        acc.x += f.x; acc.y += f.y;
    }

    float s = __ldg(&dinv[node]);
    float2 bb = __ldg((const float2*)b + lane);
    float2 o = make_float2(acc.x * s + bb.x, acc.y * s + bb.y);
    ((float2*)out)[(size_t)node * 20 + lane] = o;
}

// ---------------- launch ----------------

extern "C" void kernel_launch(void* const* d_in, const int* in_sizes, int n_in,
                              void* d_out, int out_size) {
    int i_x = -1, i_ei = -1, i_w1 = -1, i_w2 = -1, i_w3 = -1;
    int i_b1 = -1, i_b2 = -1, i_b3 = -1;
    for (int i = 0; i < n_in; i++) {
        int s = in_sizes[i];
        if      (s == 12800000) i_x  = i;
        else if (s == 3200000)  i_ei = i;
        else if (s == 8192)     i_w1 = i;
        else if (s == 4096)     i_w2 = i;
        else if (s == 2560)     i_w3 = i;
        else if (s == 40)       i_b3 = i;
        else if (s == 64)       { if (i_b1 < 0) i_b1 = i; else i_b2 = i; }
    }
    if (i_x < 0 || i_ei < 0 || i_w1 < 0 || i_b1 < 0 || i_w2 < 0 ||
        i_b2 < 0 || i_w3 < 0 || i_b3 < 0) {
        i_x = 0; i_ei = 1; i_w1 = 2; i_b1 = 3; i_w2 = 4; i_b2 = 5; i_w3 = 6; i_b3 = 7;
    }

    const float* x  = (const float*)d_in[i_x];
    const void*  ei = d_in[i_ei];
    const float* W1 = (const float*)d_in[i_w1];
    const float* b1 = (const float*)d_in[i_b1];
    const float* W2 = (const float*)d_in[i_w2];
    const float* b2 = (const float*)d_in[i_b2];
    const float* W3 = (const float*)d_in[i_w3];
    const float* b3 = (const float*)d_in[i_b3];

    const int M = in_sizes[i_x] / 128;     // 100000
    const int E = in_sizes[i_ei] / 2;      // 1600000
    float* out = (float*)d_out;

    __half2 *pA, *pB, *pC;
    float* pDinv;
    int *pDeg, *pCur, *pPtr, *pBsum, *pErow;
    cudaGetSymbolAddress((void**)&pA, g_bufA);
    cudaGetSymbolAddress((void**)&pB, g_bufB);
    cudaGetSymbolAddress((void**)&pC, g_bufC);
    cudaGetSymbolAddress((void**)&pDinv, g_dinv);
    cudaGetSymbolAddress((void**)&pDeg, g_degi);
    cudaGetSymbolAddress((void**)&pCur, g_cursor);
    cudaGetSymbolAddress((void**)&pPtr, g_ptr);
    cudaGetSymbolAddress((void**)&pBsum, g_bsum);
    cudaGetSymbolAddress((void**)&pErow, g_erow);

    const int T = 256;
    const int nbN = (M + 255) / 256;
    const int nbE = (E + T - 1) / T;
    const int gM  = (M + 127) / 128;
    const int g40 = (M + 11) / 12;

    cudaStream_t s2;
    cudaEvent_t evD, evF;
    const int NC = 4;
    cudaEvent_t evG1[NC], evG2[NC], evE2, evE3;
    bool forked = (cudaStreamCreateWithFlags(&s2, cudaStreamNonBlocking) == cudaSuccess) &&
                  (cudaEventCreateWithFlags(&evD, cudaEventDisableTiming) == cudaSuccess) &&
                  (cudaEventCreateWithFlags(&evF, cudaEventDisableTiming) == cudaSuccess) &&
                  (cudaEventCreateWithFlags(&evE2, cudaEventDisableTiming) == cudaSuccess) &&
                  (cudaEventCreateWithFlags(&evE3, cudaEventDisableTiming) == cudaSuccess);
    if (forked) {
        for (int c = 0; c < NC && forked; c++) {
            forked = (cudaEventCreateWithFlags(&evG1[c], cudaEventDisableTiming) == cudaSuccess) &&
                     (cudaEventCreateWithFlags(&evG2[c], cudaEventDisableTiming) == cudaSuccess);
        }
    }

    if (forked) {
        // ---- side stream: CSR build; main stream: GEMM1 (A, unscaled) ----
        cudaEventRecord(evD, 0);
        cudaStreamWaitEvent(s2, evD, 0);
        detect_mode_kernel<<<1, 256, 0, s2>>>(ei, 2 * E, M);
        cudaMemsetAsync(pDeg, 0, (size_t)M * sizeof(int), s2);
        deg_count_kernel<<<nbE, T, 0, s2>>>(pDeg, ei, E, M);
        scanA_kernel<<<nbN, 256, 0, s2>>>(pDeg, pPtr, pBsum, M);
        scanB_kernel<<<1, 1024, 0, s2>>>(pBsum, nbN);
        scanC_fused_kernel<<<nbN, 256, 0, s2>>>(pPtr, pBsum, pCur, pDinv, pDeg, M, E);
        fill_kernel<<<nbE, T, 0, s2>>>(ei, pCur, pErow, E, M);
        cudaEventRecord(evF, s2);

        gemm_kernel<128, 64, false, false><<<gM, 128>>>(x, W1, pDinv, pA, 0, M);
        cudaStreamWaitEvent(0, evF, 0);

        const int chunk = (M + NC - 1) / NC;

        // ---- gather1 (A->B) chunks on stream0; GEMM2 (B->C) chunks on s2 ----
        for (int c = 0; c < NC; c++) {
            int n0 = c * chunk, n1 = min(M, n0 + chunk);
            if (n0 >= n1) break;
            int gb = (n1 - n0 + 7) / 8;
            gather64h_kernel<true><<<gb, 256>>>(pA, pPtr, pErow, pDinv, b1, pB, n0, n1);
            cudaEventRecord(evG1[c], 0);
            cudaStreamWaitEvent(s2, evG1[c], 0);
            int gm = (n1 - n0 + 127) / 128;
            gemm_kernel<64, 64, true, true><<<gm, 128, 0, s2>>>(pB, W2, pDinv, pC, n0, n1);
        }
        cudaEventRecord(evE2, s2);
        cudaStreamWaitEvent(0, evE2, 0);

        // ---- gather2 (C->B) chunks on stream0; GEMM3 (B->A) chunks on s2 ----
        for (int c = 0; c < NC; c++) {
            int n0 = c * chunk, n1 = min(M, n0 + chunk);
            if (n0 >= n1) break;
            int gb = (n1 - n0 + 7) / 8;
            gather64h_kernel<false><<<gb, 256>>>(pC, pPtr, pErow, pDinv, b2, pB, n0, n1);
            cudaEventRecord(evG2[c], 0);
            cudaStreamWaitEvent(s2, evG2[c], 0);
            int gm = (n1 - n0 + 127) / 128;
            gemm_kernel<64, 40, true, true><<<gm, 128, 0, s2>>>(pB, W3, pDinv, pA, n0, n1);
        }
        cudaEventRecord(evE3, s2);
        cudaStreamWaitEvent(0, evE3, 0);

        // ---- final gather (A -> out) ----
        gather40_kernel<<<g40, 256>>>(pA, pPtr, pErow, pDinv, b3, out, M);
    } else {
        // sequential fallback
        detect_mode_kernel<<<1, 256>>>(ei, 2 * E, M);
        cudaMemsetAsync(pDeg, 0, (size_t)M * sizeof(int), 0);
        deg_count_kernel<<<nbE, T>>>(pDeg, ei, E, M);
        scanA_kernel<<<nbN, 256>>>(pDeg, pPtr, pBsum, M);
        scanB_kernel<<<1, 1024>>>(pBsum, nbN);
        scanC_fused_kernel<<<nbN, 256>>>(pPtr, pBsum, pCur, pDinv, pDeg, M, E);
        fill_kernel<<<nbE, T>>>(ei, pCur, pErow, E, M);
        gemm_kernel<128, 64, false, false><<<gM, 128>>>(x, W1, pDinv, pA, 0, M);
        gather64h_kernel<true><<<(M + 7) / 8, 256>>>(pA, pPtr, pErow, pDinv, b1, pB, 0, M);
        gemm_kernel<64, 64, true, true><<<gM, 128>>>(pB, W2, pDinv, pC, 0, M);
        gather64h_kernel<false><<<(M + 7) / 8, 256>>>(pC, pPtr, pErow, pDinv, b2, pB, 0, M);
        gemm_kernel<64, 40, true, true><<<gM, 128>>>(pB, W3, pDinv, pA, 0, M);
        gather40_kernel<<<g40, 256>>>(pA, pPtr, pErow, pDinv, b3, out, M);
    }
}

// round 14
// speedup vs baseline: 1.0635x; 1.0635x over previous
#include <cuda_runtime.h>
#include <cuda_fp16.h>
#include <cstdint>

// ---------------------------------------------------------------------------
// GCN (3-layer) on GB300 — CSR gather, fp16 xw intermediates, fused layers.
//   GEMM1: xw1 = x @ W1 (UNscaled fp16, stride 32 half2).
//   K2 (fused): per node, aggregate xw1 (applying dinv[neighbor]), h1 =
//       relu(acc*dinv+b1) in smem, then xw2 = (h1 @ W2)*dinv -> fp16.
//   K3 (fused): aggregate xw2 (prescaled), h2 = relu(acc*dinv+b2), then
//       xw3 = (h2 @ W3)*dinv -> fp16 (40 outs, padded stride).
//   K4: aggregate xw3, *dinv + b3 -> fp32 out.
//   CSR build runs on a side stream concurrent with GEMM1.
// ---------------------------------------------------------------------------

#define N_MAX 100000
#define E_MAX 1600000

static __device__ __align__(256) __half2 g_bufA[(size_t)N_MAX * 32];  // stride 32
static __device__ __align__(256) __half2 g_bufB[(size_t)N_MAX * 32];
static __device__ __align__(256) float g_dinv[N_MAX];
static __device__ int g_degi[N_MAX];
static __device__ int g_cursor[N_MAX];
static __device__ int g_ptr[N_MAX + 1];
static __device__ int g_bsum[1024];
static __device__ int g_erow[E_MAX];
static __device__ int g_mode;  // 0 = int64 indices, 1 = int32 indices

// ---------------- dtype detection ----------------
__global__ void detect_mode_kernel(const void* ei, int cnt64, int n) {
    __shared__ int bad;
    if (threadIdx.x == 0) bad = 0;
    __syncthreads();
    const long long* p = (const long long*)ei;
    int cnt = min(cnt64, 1024);
    for (int i = threadIdx.x; i < cnt; i += blockDim.x) {
        unsigned long long v = (unsigned long long)p[i];
        if (v >= (unsigned long long)n) atomicOr(&bad, 1);
    }
    __syncthreads();
    if (threadIdx.x == 0) g_mode = bad ? 1 : 0;
}

__device__ __forceinline__ int edge_idx(const void* ei, long long pos, int mode) {
    return mode ? ((const int*)ei)[pos] : (int)((const long long*)ei)[pos];
}

// ---------------- CSR build ----------------

__global__ void deg_count_kernel(int* degi, const void* ei, int E, int n) {
    int e = blockIdx.x * blockDim.x + threadIdx.x;
    if (e < E) {
        int mode = g_mode;
        unsigned c = (unsigned)edge_idx(ei, (long long)E + e, mode);  // col
        if (c < (unsigned)n) atomicAdd(&degi[c], 1);
    }
}

__global__ void scanA_kernel(const int* degi, int* ptr, int* bsum, int n) {
    __shared__ int s[256];
    int i = blockIdx.x * 256 + threadIdx.x;
    int v = (i < n) ? degi[i] : 0;
    s[threadIdx.x] = v;
    __syncthreads();
    for (int off = 1; off < 256; off <<= 1) {
        int t = (threadIdx.x >= off) ? s[threadIdx.x - off] : 0;
        __syncthreads();
        s[threadIdx.x] += t;
        __syncthreads();
    }
    if (i < n) ptr[i] = s[threadIdx.x] - v;   // exclusive within block
    if (threadIdx.x == 255) bsum[blockIdx.x] = s[255];
}

__global__ void scanB_kernel(int* bsum, int nb) {
    __shared__ int s[1024];
    int v = (threadIdx.x < nb) ? bsum[threadIdx.x] : 0;
    s[threadIdx.x] = v;
    __syncthreads();
    for (int off = 1; off < 1024; off <<= 1) {
        int t = (threadIdx.x >= off) ? s[threadIdx.x - off] : 0;
        __syncthreads();
        s[threadIdx.x] += t;
        __syncthreads();
    }
    if (threadIdx.x < nb) bsum[threadIdx.x] = s[threadIdx.x] - v;  // exclusive
}

__global__ void scanC_fused_kernel(int* ptr, const int* bsum, int* cursor,
                                   float* dinv, const int* degi, int n, int E) {
    int i = blockIdx.x * 256 + threadIdx.x;
    if (i < n) {
        int p = ptr[i] + bsum[blockIdx.x];
        ptr[i] = p;
        cursor[i] = p;
        dinv[i] = rsqrtf(1.0f + (float)degi[i]);     // +1 self loop
    }
    if (i == 0) ptr[n] = E;
}

__global__ void fill_kernel(const void* ei, int* cursor, int* erow, int E, int n) {
    int e = blockIdx.x * blockDim.x + threadIdx.x;
    if (e < E) {
        int mode = g_mode;
        unsigned r = (unsigned)edge_idx(ei, e, mode);
        unsigned c = (unsigned)edge_idx(ei, (long long)E + e, mode);
        if (r >= (unsigned)n || c >= (unsigned)n) return;
        int pos = atomicAdd(&cursor[c], 1);
        erow[pos] = (int)r;
    }
}

// ---------------- packed f32x2 FMA ----------------

__device__ __forceinline__ void fma2(unsigned long long& d,
                                     unsigned long long a,
                                     unsigned long long b) {
    asm("fma.rn.f32x2 %0, %1, %2, %3;" : "=l"(d) : "l"(a), "l"(b), "l"(d));
}

__device__ __forceinline__ unsigned long long pack_dup(float v) {
    unsigned long long r;
    asm("mov.b64 %0, {%1, %2};" : "=l"(r) : "f"(v), "f"(v));
    return r;
}

// ---------------- GEMM1: x(f32,128) @ W1 -> xw1 (fp16, unscaled) ------------

__global__ void gemm1_kernel(const float* __restrict__ X,
                             const float* __restrict__ W,
                             __half2* __restrict__ xwh,
                             int M) {
    constexpr int DIN = 128, DOUT = 64;
    __shared__ __align__(16) float Ws[DIN * DOUT];
    const int tid = threadIdx.x;           // 0..127
    const int row = blockIdx.x * 128 + tid;

    for (int i = tid; i < DIN * DOUT; i += 128) Ws[i] = W[i];
    __syncthreads();

    unsigned long long a2[DOUT / 2];
#pragma unroll
    for (int j = 0; j < DOUT / 2; j++) a2[j] = 0ull;

    const bool act = (row < M);

#pragma unroll
    for (int k0 = 0; k0 < DIN; k0 += 16) {
        float xr[16];
        if (act) {
            const float4* src = (const float4*)(X + (size_t)row * DIN + k0);
#pragma unroll
            for (int q = 0; q < 4; q++) {
                float4 v = __ldg(src + q);
                xr[q * 4] = v.x; xr[q * 4 + 1] = v.y;
                xr[q * 4 + 2] = v.z; xr[q * 4 + 3] = v.w;
            }
        } else {
#pragma unroll
            for (int q = 0; q < 16; q++) xr[q] = 0.f;
        }
#pragma unroll
        for (int k = 0; k < 16; k++) {
            unsigned long long xv2 = pack_dup(xr[k]);
            const float* wrow = &Ws[(k0 + k) * DOUT];
#pragma unroll
            for (int j = 0; j < DOUT; j += 4) {
                ulonglong2 ww = *(const ulonglong2*)&wrow[j];
                fma2(a2[j / 2],     xv2, ww.x);
                fma2(a2[j / 2 + 1], xv2, ww.y);
            }
        }
    }

    if (act) {
        __half2* dst = xwh + (size_t)row * 32;
#pragma unroll
        for (int p = 0; p < DOUT / 2; p += 2) {
            float x0, x1, x2, x3;
            asm("mov.b64 {%0, %1}, %2;" : "=f"(x0), "=f"(x1) : "l"(a2[p]));
            asm("mov.b64 {%0, %1}, %2;" : "=f"(x2), "=f"(x3) : "l"(a2[p + 1]));
            uint2 pack;
            __half2 h0 = __floats2half2_rn(x0, x1);
            __half2 h1 = __floats2half2_rn(x2, x3);
            pack.x = *(unsigned*)&h0;
            pack.y = *(unsigned*)&h1;
            *(uint2*)&dst[p] = pack;
        }
    }
}

// ---------------- fused gather + next-layer GEMM ----------------------------
// 8 nodes/block (warp per node). NSCALE: apply dinv[neighbor] during gather.
// DOUT_N = next-layer width (64 or 40). W packed as float2 pairs in smem.

template <int DOUT_N, bool NSCALE>
__global__ void fused_gather_gemm_kernel(const __half2* __restrict__ xwh,
                                         const int* __restrict__ ptr,
                                         const int* __restrict__ erow,
                                         const float* __restrict__ dinv,
                                         const float* __restrict__ bias,
                                         const float* __restrict__ Wn,
                                         __half2* __restrict__ xw_out,
                                         int n) {
    constexpr int PAIRS = DOUT_N / 2;                 // 32 or 20
    __shared__ __align__(16) unsigned long long w_s[64 * PAIRS];
    __shared__ float h_s[8][64];

    const int tid = threadIdx.x;
    // stage W (64 x DOUT_N floats = 64*PAIRS float2-pairs)
    for (int i = tid; i < 64 * PAIRS; i += 256)
        w_s[i] = ((const unsigned long long*)Wn)[i];
    __syncthreads();

    const int lane = tid & 31;
    const int w = tid >> 5;
    const int node = blockIdx.x * 8 + w;
    if (node >= n) return;

    int start = __ldg(&ptr[node]);
    int end   = __ldg(&ptr[node + 1]);
    float sn = __ldg(&dinv[node]);

    // ---- gather ----
    float2 self = __half22float2(__ldg(&xwh[(size_t)node * 32 + lane]));
    float2 acc;
    if (NSCALE) { acc.x = self.x * sn; acc.y = self.y * sn; }
    else        { acc = self; }

    int cnt = end - start;
    int j = start, j8 = start + (cnt & ~7);
    for (; j < j8; j += 8) {
        int ids[8];
#pragma unroll
        for (int k = 0; k < 8; k++) ids[k] = __ldg(&erow[j + k]);
#pragma unroll
        for (int k = 0; k < 8; k++) {
            float2 f = __half22float2(__ldg(&xwh[(size_t)ids[k] * 32 + lane]));
            if (NSCALE) {
                float sr = __ldg(&dinv[ids[k]]);
                acc.x += f.x * sr; acc.y += f.y * sr;
            } else {
                acc.x += f.x; acc.y += f.y;
            }
        }
    }
    for (; j < end; j++) {
        int id = __ldg(&erow[j]);
        float2 f = __half22float2(__ldg(&xwh[(size_t)id * 32 + lane]));
        if (NSCALE) {
            float sr = __ldg(&dinv[id]);
            acc.x += f.x * sr; acc.y += f.y * sr;
        } else {
            acc.x += f.x; acc.y += f.y;
        }
    }

    // ---- epilogue: h = relu(acc*sn + b) -> smem ----
    float2 bb = __ldg((const float2*)bias + lane);
    h_s[w][2 * lane]     = fmaxf(acc.x * sn + bb.x, 0.f);
    h_s[w][2 * lane + 1] = fmaxf(acc.y * sn + bb.y, 0.f);
    __syncwarp();

    // ---- next-layer GEMM: xw_out[node] = (h @ Wn) * sn ----
    if (lane < PAIRS) {
        unsigned long long o2 = 0ull;
        const float* hrow = h_s[w];
#pragma unroll
        for (int k = 0; k < 64; k++) {
            fma2(o2, pack_dup(hrow[k]), w_s[k * PAIRS + lane]);
        }
        float o0, o1;
        asm("mov.b64 {%0, %1}, %2;" : "=f"(o0), "=f"(o1) : "l"(o2));
        xw_out[(size_t)node * 32 + lane] = __floats2half2_rn(o0 * sn, o1 * sn);
    }
}

// ---------------- final gather: D=40, fp32 out ------------------------------

__global__ void gather40_kernel(const __half2* __restrict__ xwh,
                                const int* __restrict__ ptr,
                                const int* __restrict__ erow,
                                const float* __restrict__ dinv,
                                const float* __restrict__ b,
                                float* __restrict__ out,
                                int n) {
    int tid = threadIdx.x;
    if (tid >= 240) return;                  // 12 nodes * 20 threads
    int nl = tid / 20;
    int lane = tid - nl * 20;                // feature pair 0..19
    int node = blockIdx.x * 12 + nl;
    if (node >= n) return;

    int start = __ldg(&ptr[node]);
    int end   = __ldg(&ptr[node + 1]);

    float2 acc = __half22float2(__ldg(&xwh[(size_t)node * 32 + lane]));  // self

    int cnt = end - start;
    int j = start, j8 = start + (cnt & ~7);
    for (; j < j8; j += 8) {
        int ids[8];
#pragma unroll
        for (int k = 0; k < 8; k++) ids[k] = __ldg(&erow[j + k]);
#pragma unroll
        for (int k = 0; k < 8; k++) {
            float2 f = __half22float2(__ldg(&xwh[(size_t)ids[k] * 32 + lane]));
            acc.x += f.x; acc.y += f.y;
        }
    }
    for (; j < end; j++) {
        float2 f = __half22float2(__ldg(&xwh[(size_t)__ldg(&erow[j]) * 32 + lane]));
        acc.x += f.x; acc.y += f.y;
    }

    float s = __ldg(&dinv[node]);
    float2 bb = __ldg((const float2*)b + lane);
    float2 o = make_float2(acc.x * s + bb.x, acc.y * s + bb.y);
    ((float2*)out)[(size_t)node * 20 + lane] = o;
}

// ---------------- launch ----------------

extern "C" void kernel_launch(void* const* d_in, const int* in_sizes, int n_in,
                              void* d_out, int out_size) {
    int i_x = -1, i_ei = -1, i_w1 = -1, i_w2 = -1, i_w3 = -1;
    int i_b1 = -1, i_b2 = -1, i_b3 = -1;
    for (int i = 0; i < n_in; i++) {
        int s = in_sizes[i];
        if      (s == 12800000) i_x  = i;
        else if (s == 3200000)  i_ei = i;
        else if (s == 8192)     i_w1 = i;
        else if (s == 4096)     i_w2 = i;
        else if (s == 2560)     i_w3 = i;
        else if (s == 40)       i_b3 = i;
        else if (s == 64)       { if (i_b1 < 0) i_b1 = i; else i_b2 = i; }
    }
    if (i_x < 0 || i_ei < 0 || i_w1 < 0 || i_b1 < 0 || i_w2 < 0 ||
        i_b2 < 0 || i_w3 < 0 || i_b3 < 0) {
        i_x = 0; i_ei = 1; i_w1 = 2; i_b1 = 3; i_w2 = 4; i_b2 = 5; i_w3 = 6; i_b3 = 7;
    }

    const float* x  = (const float*)d_in[i_x];
    const void*  ei = d_in[i_ei];
    const float* W1 = (const float*)d_in[i_w1];
    const float* b1 = (const float*)d_in[i_b1];
    const float* W2 = (const float*)d_in[i_w2];
    const float* b2 = (const float*)d_in[i_b2];
    const float* W3 = (const float*)d_in[i_w3];
    const float* b3 = (const float*)d_in[i_b3];

    const int M = in_sizes[i_x] / 128;     // 100000
    const int E = in_sizes[i_ei] / 2;      // 1600000
    float* out = (float*)d_out;

    __half2 *pA, *pB;
    float* pDinv;
    int *pDeg, *pCur, *pPtr, *pBsum, *pErow;
    cudaGetSymbolAddress((void**)&pA, g_bufA);
    cudaGetSymbolAddress((void**)&pB, g_bufB);
    cudaGetSymbolAddress((void**)&pDinv, g_dinv);
    cudaGetSymbolAddress((void**)&pDeg, g_degi);
    cudaGetSymbolAddress((void**)&pCur, g_cursor);
    cudaGetSymbolAddress((void**)&pPtr, g_ptr);
    cudaGetSymbolAddress((void**)&pBsum, g_bsum);
    cudaGetSymbolAddress((void**)&pErow, g_erow);

    const int T = 256;
    const int nbN = (M + 255) / 256;
    const int nbE = (E + T - 1) / T;
    const int gM  = (M + 127) / 128;
    const int gF  = (M + 7) / 8;
    const int g40 = (M + 11) / 12;

    cudaStream_t s2;
    cudaEvent_t evD, evF;
    bool forked = (cudaStreamCreateWithFlags(&s2, cudaStreamNonBlocking) == cudaSuccess) &&
                  (cudaEventCreateWithFlags(&evD, cudaEventDisableTiming) == cudaSuccess) &&
                  (cudaEventCreateWithFlags(&evF, cudaEventDisableTiming) == cudaSuccess);

    if (forked) {
        // side stream: complete CSR build; main stream: GEMM1 (unscaled)
        cudaEventRecord(evD, 0);
        cudaStreamWaitEvent(s2, evD, 0);
        detect_mode_kernel<<<1, 256, 0, s2>>>(ei, 2 * E, M);
        cudaMemsetAsync(pDeg, 0, (size_t)M * sizeof(int), s2);
        deg_count_kernel<<<nbE, T, 0, s2>>>(pDeg, ei, E, M);
        scanA_kernel<<<nbN, 256, 0, s2>>>(pDeg, pPtr, pBsum, M);
        scanB_kernel<<<1, 1024, 0, s2>>>(pBsum, nbN);
        scanC_fused_kernel<<<nbN, 256, 0, s2>>>(pPtr, pBsum, pCur, pDinv, pDeg, M, E);
        fill_kernel<<<nbE, T, 0, s2>>>(ei, pCur, pErow, E, M);
        cudaEventRecord(evF, s2);

        gemm1_kernel<<<gM, 128>>>(x, W1, pA, M);
        cudaStreamWaitEvent(0, evF, 0);
    } else {
        detect_mode_kernel<<<1, 256>>>(ei, 2 * E, M);
        cudaMemsetAsync(pDeg, 0, (size_t)M * sizeof(int), 0);
        deg_count_kernel<<<nbE, T>>>(pDeg, ei, E, M);
        scanA_kernel<<<nbN, 256>>>(pDeg, pPtr, pBsum, M);
        scanB_kernel<<<1, 1024>>>(pBsum, nbN);
        scanC_fused_kernel<<<nbN, 256>>>(pPtr, pBsum, pCur, pDinv, pDeg, M, E);
        fill_kernel<<<nbE, T>>>(ei, pCur, pErow, E, M);
        gemm1_kernel<<<gM, 128>>>(x, W1, pA, M);
    }

    // K2: gather1 (A, apply dinv[nbr]) + GEMM2 -> B (prescaled)
    fused_gather_gemm_kernel<64, true><<<gF, 256>>>(pA, pPtr, pErow, pDinv,
                                                    b1, W2, pB, M);
    // K3: gather2 (B) + GEMM3 -> A (prescaled, 40 outs)
    fused_gather_gemm_kernel<40, false><<<gF, 256>>>(pB, pPtr, pErow, pDinv,
                                                     b2, W3, pA, M);
    // K4: final gather -> out
    gather40_kernel<<<g40, 256>>>(pA, pPtr, pErow, pDinv, b3, out, M);
}

// round 16
// speedup vs baseline: 1.1682x; 1.0985x over previous
#include <cuda_runtime.h>
#include <cuda_fp16.h>
#include <cstdint>

// ---------------------------------------------------------------------------
// GCN (3-layer) on GB300 — CSR gather (vectorized LDG.128), fp16 intermediates.
//   GEMM1: xw1 = x @ W1 (fp16, stride 32 half2); then prescale xw1 *= dinv.
//   GEMM2/3 prescale by dinv[row] directly.
//   gatherNv: warp per node; lane (g=lane>>3, c=lane&7): one LDG.128 loads
//   16B chunk c of edge-slot g's row -> 4 edges per instruction; fp32 partials
//   reduced across g via shfl_xor; epilogue on lanes g==0.
//   CSR build runs on a side stream concurrent with GEMM1.
// ---------------------------------------------------------------------------

#define N_MAX 100000
#define E_MAX 1600000

static __device__ __align__(256) __half2 g_bufA[(size_t)N_MAX * 32];  // stride 32
static __device__ __align__(256) __half2 g_bufB[(size_t)N_MAX * 32];
static __device__ __align__(256) float g_dinv[N_MAX];
static __device__ int g_degi[N_MAX];
static __device__ int g_cursor[N_MAX];
static __device__ int g_ptr[N_MAX + 1];
static __device__ int g_bsum[1024];
static __device__ int g_erow[E_MAX];
static __device__ int g_mode;  // 0 = int64 indices, 1 = int32 indices

// ---------------- dtype detection ----------------
__global__ void detect_mode_kernel(const void* ei, int cnt64, int n) {
    __shared__ int bad;
    if (threadIdx.x == 0) bad = 0;
    __syncthreads();
    const long long* p = (const long long*)ei;
    int cnt = min(cnt64, 1024);
    for (int i = threadIdx.x; i < cnt; i += blockDim.x) {
        unsigned long long v = (unsigned long long)p[i];
        if (v >= (unsigned long long)n) atomicOr(&bad, 1);
    }
    __syncthreads();
    if (threadIdx.x == 0) g_mode = bad ? 1 : 0;
}

__device__ __forceinline__ int edge_idx(const void* ei, long long pos, int mode) {
    return mode ? ((const int*)ei)[pos] : (int)((const long long*)ei)[pos];
}

// ---------------- CSR build ----------------

__global__ void deg_count_kernel(int* degi, const void* ei, int E, int n) {
    int e = blockIdx.x * blockDim.x + threadIdx.x;
    if (e < E) {
        int mode = g_mode;
        unsigned c = (unsigned)edge_idx(ei, (long long)E + e, mode);  // col
        if (c < (unsigned)n) atomicAdd(&degi[c], 1);
    }
}

__global__ void scanA_kernel(const int* degi, int* ptr, int* bsum, int n) {
    __shared__ int s[256];
    int i = blockIdx.x * 256 + threadIdx.x;
    int v = (i < n) ? degi[i] : 0;
    s[threadIdx.x] = v;
    __syncthreads();
    for (int off = 1; off < 256; off <<= 1) {
        int t = (threadIdx.x >= off) ? s[threadIdx.x - off] : 0;
        __syncthreads();
        s[threadIdx.x] += t;
        __syncthreads();
    }
    if (i < n) ptr[i] = s[threadIdx.x] - v;   // exclusive within block
    if (threadIdx.x == 255) bsum[blockIdx.x] = s[255];
}

__global__ void scanB_kernel(int* bsum, int nb) {
    __shared__ int s[1024];
    int v = (threadIdx.x < nb) ? bsum[threadIdx.x] : 0;
    s[threadIdx.x] = v;
    __syncthreads();
    for (int off = 1; off < 1024; off <<= 1) {
        int t = (threadIdx.x >= off) ? s[threadIdx.x - off] : 0;
        __syncthreads();
        s[threadIdx.x] += t;
        __syncthreads();
    }
    if (threadIdx.x < nb) bsum[threadIdx.x] = s[threadIdx.x] - v;  // exclusive
}

__global__ void scanC_fused_kernel(int* ptr, const int* bsum, int* cursor,
                                   float* dinv, const int* degi, int n, int E) {
    int i = blockIdx.x * 256 + threadIdx.x;
    if (i < n) {
        int p = ptr[i] + bsum[blockIdx.x];
        ptr[i] = p;
        cursor[i] = p;
        dinv[i] = rsqrtf(1.0f + (float)degi[i]);     // +1 self loop
    }
    if (i == 0) ptr[n] = E;
}

__global__ void fill_kernel(const void* ei, int* cursor, int* erow, int E, int n) {
    int e = blockIdx.x * blockDim.x + threadIdx.x;
    if (e < E) {
        int mode = g_mode;
        unsigned r = (unsigned)edge_idx(ei, e, mode);
        unsigned c = (unsigned)edge_idx(ei, (long long)E + e, mode);
        if (r >= (unsigned)n || c >= (unsigned)n) return;
        int pos = atomicAdd(&cursor[c], 1);
        erow[pos] = (int)r;
    }
}

// ---------------- packed f32x2 FMA ----------------

__device__ __forceinline__ void fma2(unsigned long long& d,
                                     unsigned long long a,
                                     unsigned long long b) {
    asm("fma.rn.f32x2 %0, %1, %2, %3;" : "=l"(d) : "l"(a), "l"(b), "l"(d));
}

__device__ __forceinline__ unsigned long long pack_dup(float v) {
    unsigned long long r;
    asm("mov.b64 %0, {%1, %2};" : "=l"(r) : "f"(v), "f"(v));
    return r;
}

// ---------------- GEMM (+ optional dinv scale) -> half2, stride 32 ----------

template <int DIN, int DOUT, bool HALF_IN, bool SCALE>
__global__ void gemm_kernel(const void* __restrict__ Xv,
                            const float* __restrict__ W,
                            const float* __restrict__ dinv,
                            __half2* __restrict__ xwh,
                            int M) {
    __shared__ __align__(16) float Ws[DIN * DOUT];
    const int tid = threadIdx.x;           // 0..127
    const int row = blockIdx.x * 128 + tid;

    for (int i = tid; i < DIN * DOUT; i += 128) Ws[i] = W[i];
    __syncthreads();

    unsigned long long a2[DOUT / 2];
#pragma unroll
    for (int j = 0; j < DOUT / 2; j++) a2[j] = 0ull;

    const bool act = (row < M);

#pragma unroll
    for (int k0 = 0; k0 < DIN; k0 += 16) {
        float xr[16];
        if (act) {
            if (HALF_IN) {
                const uint4* src = (const uint4*)((const __half*)Xv + (size_t)row * DIN + k0);
                uint4 u0 = __ldg(src);
                uint4 u1 = __ldg(src + 1);
                const unsigned* uu = &u0.x;
#pragma unroll
                for (int q = 0; q < 4; q++) {
                    float2 f = __half22float2(*(const __half2*)&uu[q]);
                    xr[q * 2] = f.x; xr[q * 2 + 1] = f.y;
                }
                const unsigned* vv = &u1.x;
#pragma unroll
                for (int q = 0; q < 4; q++) {
                    float2 f = __half22float2(*(const __half2*)&vv[q]);
                    xr[8 + q * 2] = f.x; xr[8 + q * 2 + 1] = f.y;
                }
            } else {
                const float4* src = (const float4*)((const float*)Xv + (size_t)row * DIN + k0);
#pragma unroll
                for (int q = 0; q < 4; q++) {
                    float4 v = __ldg(src + q);
                    xr[q * 4] = v.x; xr[q * 4 + 1] = v.y;
                    xr[q * 4 + 2] = v.z; xr[q * 4 + 3] = v.w;
                }
            }
        } else {
#pragma unroll
            for (int q = 0; q < 16; q++) xr[q] = 0.f;
        }
#pragma unroll
        for (int k = 0; k < 16; k++) {
            unsigned long long xv2 = pack_dup(xr[k]);
            const float* wrow = &Ws[(k0 + k) * DOUT];
#pragma unroll
            for (int j = 0; j < DOUT; j += 4) {
                ulonglong2 ww = *(const ulonglong2*)&wrow[j];
                fma2(a2[j / 2],     xv2, ww.x);
                fma2(a2[j / 2 + 1], xv2, ww.y);
            }
        }
    }

    if (act) {
        float s = SCALE ? dinv[row] : 1.0f;
        __half2* dst = xwh + (size_t)row * 32;      // padded stride
#pragma unroll
        for (int p = 0; p < DOUT / 2; p += 2) {
            float x0, x1, x2, x3;
            asm("mov.b64 {%0, %1}, %2;" : "=f"(x0), "=f"(x1) : "l"(a2[p]));
            asm("mov.b64 {%0, %1}, %2;" : "=f"(x2), "=f"(x3) : "l"(a2[p + 1]));
            uint2 pack;
            __half2 h0 = __floats2half2_rn(x0 * s, x1 * s);
            __half2 h1 = __floats2half2_rn(x2 * s, x3 * s);
            pack.x = *(unsigned*)&h0;
            pack.y = *(unsigned*)&h1;
            *(uint2*)&dst[p] = pack;
        }
    }
}

// ---------------- prescale: xw *= dinv[row] (row stride 32 half2) -----------

__global__ void prescale_kernel(__half2* __restrict__ xw,
                                const float* __restrict__ dinv, int n) {
    int i = blockIdx.x * blockDim.x + threadIdx.x;   // one uint4 = 4 half2
    if (i >= n * 8) return;
    int row = i >> 3;
    float s = __ldg(&dinv[row]);
    uint4 v = *((uint4*)xw + i);
    unsigned* u = &v.x;
#pragma unroll
    for (int q = 0; q < 4; q++) {
        float2 f = __half22float2(*(__half2*)&u[q]);
        __half2 h = __floats2half2_rn(f.x * s, f.y * s);
        u[q] = *(unsigned*)&h;
    }
    *((uint4*)xw + i) = v;
}

// ---------------- vectorized gather: D=64 -----------------------------------
// Warp per node. Lane: g=lane>>3 (edge slot 0..3), c=lane&7 (16B chunk).
// One LDG.128 covers chunk c of 4 edge rows. fp32 partials, shfl_xor reduce.

__device__ __forceinline__ void acc_u4(float2* acc, uint4 v) {
    const unsigned* u = &v.x;
#pragma unroll
    for (int q = 0; q < 4; q++) {
        float2 f = __half22float2(*(const __half2*)&u[q]);
        acc[q].x += f.x; acc[q].y += f.y;
    }
}

__global__ void gather64v_kernel(const __half2* __restrict__ xwh,
                                 const int* __restrict__ ptr,
                                 const int* __restrict__ erow,
                                 const float* __restrict__ dinv,
                                 const float* __restrict__ bias,
                                 __half2* __restrict__ out,
                                 int n) {
    const int lane = threadIdx.x & 31;
    const int g = lane >> 3;
    const int c = lane & 7;
    const int node = blockIdx.x * 8 + (threadIdx.x >> 5);
    if (node >= n) return;

    const int start = __ldg(&ptr[node]);
    const int end   = __ldg(&ptr[node + 1]);

    float2 acc[4];
#pragma unroll
    for (int q = 0; q < 4; q++) acc[q] = make_float2(0.f, 0.f);

    // 8 edges per iteration (two 4-edge vector loads in flight)
    for (int j = start; j < end; j += 8) {
        int j0 = j + g, j1 = j + 4 + g;
        int id0 = (j0 < end) ? __ldg(&erow[j0]) : -1;
        int id1 = (j1 < end) ? __ldg(&erow[j1]) : -1;
        uint4 v0 = make_uint4(0, 0, 0, 0), v1 = make_uint4(0, 0, 0, 0);
        if (id0 >= 0) v0 = __ldg((const uint4*)(xwh + (size_t)id0 * 32) + c);
        if (id1 >= 0) v1 = __ldg((const uint4*)(xwh + (size_t)id1 * 32) + c);
        acc_u4(acc, v0);
        acc_u4(acc, v1);
    }

    // reduce across edge slots (lanes differing in bits 3,4 of lane id)
#pragma unroll
    for (int off = 8; off <= 16; off <<= 1) {
#pragma unroll
        for (int q = 0; q < 4; q++) {
            acc[q].x += __shfl_xor_sync(0xffffffffu, acc[q].x, off);
            acc[q].y += __shfl_xor_sync(0xffffffffu, acc[q].y, off);
        }
    }

    if (g == 0) {
        // self row (prescaled)
        uint4 sv = __ldg((const uint4*)(xwh + (size_t)node * 32) + c);
        const unsigned* su = &sv.x;
        float s = __ldg(&dinv[node]);
        float4 b0 = __ldg((const float4*)(bias + c * 8));
        float4 b1 = __ldg((const float4*)(bias + c * 8 + 4));
        const float* bb = &b0.x;  // b0,b1 contiguous in regs? safer: array
        float bf[8] = {b0.x, b0.y, b0.z, b0.w, b1.x, b1.y, b1.z, b1.w};
        (void)bb;
        uint4 ov;
        unsigned* ou = &ov.x;
#pragma unroll
        for (int q = 0; q < 4; q++) {
            float2 sf = __half22float2(*(const __half2*)&su[q]);
            float ox = fmaxf((acc[q].x + sf.x) * s + bf[2 * q], 0.f);
            float oy = fmaxf((acc[q].y + sf.y) * s + bf[2 * q + 1], 0.f);
            __half2 h = __floats2half2_rn(ox, oy);
            ou[q] = *(unsigned*)&h;
        }
        *((uint4*)(out + (size_t)node * 32) + c) = ov;
    }
}

// ---------------- vectorized gather: final D=40, fp32 out -------------------
// Chunks c=0..4 active (rows padded to stride 32 half2). No relu.

__global__ void gather40v_kernel(const __half2* __restrict__ xwh,
                                 const int* __restrict__ ptr,
                                 const int* __restrict__ erow,
                                 const float* __restrict__ dinv,
                                 const float* __restrict__ bias,
                                 float* __restrict__ out,
                                 int n) {
    const int lane = threadIdx.x & 31;
    const int g = lane >> 3;
    const int c = lane & 7;
    const int node = blockIdx.x * 8 + (threadIdx.x >> 5);
    if (node >= n) return;

    const int start = __ldg(&ptr[node]);
    const int end   = __ldg(&ptr[node + 1]);
    const bool live = (c < 5);

    float2 acc[4];
#pragma unroll
    for (int q = 0; q < 4; q++) acc[q] = make_float2(0.f, 0.f);

    for (int j = start; j < end; j += 8) {
        int j0 = j + g, j1 = j + 4 + g;
        int id0 = (live && j0 < end) ? __ldg(&erow[j0]) : -1;
        int id1 = (live && j1 < end) ? __ldg(&erow[j1]) : -1;
        uint4 v0 = make_uint4(0, 0, 0, 0), v1 = make_uint4(0, 0, 0, 0);
        if (id0 >= 0) v0 = __ldg((const uint4*)(xwh + (size_t)id0 * 32) + c);
        if (id1 >= 0) v1 = __ldg((const uint4*)(xwh + (size_t)id1 * 32) + c);
        acc_u4(acc, v0);
        acc_u4(acc, v1);
    }

#pragma unroll
    for (int off = 8; off <= 16; off <<= 1) {
#pragma unroll
        for (int q = 0; q < 4; q++) {
            acc[q].x += __shfl_xor_sync(0xffffffffu, acc[q].x, off);
            acc[q].y += __shfl_xor_sync(0xffffffffu, acc[q].y, off);
        }
    }

    if (g == 0 && live) {
        uint4 sv = __ldg((const uint4*)(xwh + (size_t)node * 32) + c);
        const unsigned* su = &sv.x;
        float s = __ldg(&dinv[node]);
        float4 b0 = __ldg((const float4*)(bias + c * 8));
        float4 b1 = __ldg((const float4*)(bias + c * 8 + 4));
        float bf[8] = {b0.x, b0.y, b0.z, b0.w, b1.x, b1.y, b1.z, b1.w};
        float o[8];
#pragma unroll
        for (int q = 0; q < 4; q++) {
            float2 sf = __half22float2(*(const __half2*)&su[q]);
            o[2 * q]     = (acc[q].x + sf.x) * s + bf[2 * q];
            o[2 * q + 1] = (acc[q].y + sf.y) * s + bf[2 * q + 1];
        }
        float* dst = out + (size_t)node * 40 + c * 8;
        *(float4*)dst       = make_float4(o[0], o[1], o[2], o[3]);
        *(float4*)(dst + 4) = make_float4(o[4], o[5], o[6], o[7]);
    }
}

// ---------------- launch ----------------

extern "C" void kernel_launch(void* const* d_in, const int* in_sizes, int n_in,
                              void* d_out, int out_size) {
    int i_x = -1, i_ei = -1, i_w1 = -1, i_w2 = -1, i_w3 = -1;
    int i_b1 = -1, i_b2 = -1, i_b3 = -1;
    for (int i = 0; i < n_in; i++) {
        int s = in_sizes[i];
        if      (s == 12800000) i_x  = i;
        else if (s == 3200000)  i_ei = i;
        else if (s == 8192)     i_w1 = i;
        else if (s == 4096)     i_w2 = i;
        else if (s == 2560)     i_w3 = i;
        else if (s == 40)       i_b3 = i;
        else if (s == 64)       { if (i_b1 < 0) i_b1 = i; else i_b2 = i; }
    }
    if (i_x < 0 || i_ei < 0 || i_w1 < 0 || i_b1 < 0 || i_w2 < 0 ||
        i_b2 < 0 || i_w3 < 0 || i_b3 < 0) {
        i_x = 0; i_ei = 1; i_w1 = 2; i_b1 = 3; i_w2 = 4; i_b2 = 5; i_w3 = 6; i_b3 = 7;
    }

    const float* x  = (const float*)d_in[i_x];
    const void*  ei = d_in[i_ei];
    const float* W1 = (const float*)d_in[i_w1];
    const float* b1 = (const float*)d_in[i_b1];
    const float* W2 = (const float*)d_in[i_w2];
    const float* b2 = (const float*)d_in[i_b2];
    const float* W3 = (const float*)d_in[i_w3];
    const float* b3 = (const float*)d_in[i_b3];

    const int M = in_sizes[i_x] / 128;     // 100000
    const int E = in_sizes[i_ei] / 2;      // 1600000
    float* out = (float*)d_out;

    __half2 *pA, *pB;
    float* pDinv;
    int *pDeg, *pCur, *pPtr, *pBsum, *pErow;
    cudaGetSymbolAddress((void**)&pA, g_bufA);
    cudaGetSymbolAddress((void**)&pB, g_bufB);
    cudaGetSymbolAddress((void**)&pDinv, g_dinv);
    cudaGetSymbolAddress((void**)&pDeg, g_degi);
    cudaGetSymbolAddress((void**)&pCur, g_cursor);
    cudaGetSymbolAddress((void**)&pPtr, g_ptr);
    cudaGetSymbolAddress((void**)&pBsum, g_bsum);
    cudaGetSymbolAddress((void**)&pErow, g_erow);

    const int T = 256;
    const int nbN = (M + 255) / 256;
    const int nbE = (E + T - 1) / T;
    const int gM  = (M + 127) / 128;
    const int gV  = (M + 7) / 8;
    const int gP  = (M * 8 + T - 1) / T;

    cudaStream_t s2;
    cudaEvent_t evD, evF;
    bool forked = (cudaStreamCreateWithFlags(&s2, cudaStreamNonBlocking) == cudaSuccess) &&
                  (cudaEventCreateWithFlags(&evD, cudaEventDisableTiming) == cudaSuccess) &&
                  (cudaEventCreateWithFlags(&evF, cudaEventDisableTiming) == cudaSuccess);

    if (forked) {
        // side stream: complete CSR build; main stream: GEMM1 (unscaled)
        cudaEventRecord(evD, 0);
        cudaStreamWaitEvent(s2, evD, 0);
        detect_mode_kernel<<<1, 256, 0, s2>>>(ei, 2 * E, M);
        cudaMemsetAsync(pDeg, 0, (size_t)M * sizeof(int), s2);
        deg_count_kernel<<<nbE, T, 0, s2>>>(pDeg, ei, E, M);
        scanA_kernel<<<nbN, 256, 0, s2>>>(pDeg, pPtr, pBsum, M);
        scanB_kernel<<<1, 1024, 0, s2>>>(pBsum, nbN);
        scanC_fused_kernel<<<nbN, 256, 0, s2>>>(pPtr, pBsum, pCur, pDinv, pDeg, M, E);
        fill_kernel<<<nbE, T, 0, s2>>>(ei, pCur, pErow, E, M);
        cudaEventRecord(evF, s2);

        gemm_kernel<128, 64, false, false><<<gM, 128>>>(x, W1, pDinv, pA, M);
        cudaStreamWaitEvent(0, evF, 0);
    } else {
        detect_mode_kernel<<<1, 256>>>(ei, 2 * E, M);
        cudaMemsetAsync(pDeg, 0, (size_t)M * sizeof(int), 0);
        deg_count_kernel<<<nbE, T>>>(pDeg, ei, E, M);
        scanA_kernel<<<nbN, 256>>>(pDeg, pPtr, pBsum, M);
        scanB_kernel<<<1, 1024>>>(pBsum, nbN);
        scanC_fused_kernel<<<nbN, 256>>>(pPtr, pBsum, pCur, pDinv, pDeg, M, E);
        fill_kernel<<<nbE, T>>>(ei, pCur, pErow, E, M);
        gemm_kernel<128, 64, false, false><<<gM, 128>>>(x, W1, pDinv, pA, M);
    }

    // prescale xw1 by dinv (needs both GEMM1 and dinv ready)
    prescale_kernel<<<gP, T>>>(pA, pDinv, M);

    // Layer 1 aggregation (A -> B)
    gather64v_kernel<<<gV, 256>>>(pA, pPtr, pErow, pDinv, b1, pB, M);

    // Layer 2 (B -> A prescaled), aggregation (A -> B)
    gemm_kernel<64, 64, true, true><<<gM, 128>>>(pB, W2, pDinv, pA, M);
    gather64v_kernel<<<gV, 256>>>(pA, pPtr, pErow, pDinv, b2, pB, M);

    // Layer 3 (B -> A prescaled, 40 outs), final aggregation (A -> out)
    gemm_kernel<64, 40, true, true><<<gM, 128>>>(pB, W3, pDinv, pA, M);
    gather40v_kernel<<<gV, 256>>>(pA, pPtr, pErow, pDinv, b3, out, M);
}